// round 1
// baseline (speedup 1.0000x reference)
#include <cuda_runtime.h>

#define SEQ 1024
#define NB  48
#define NROWS (NB * SEQ)          // 49152 rows of 9 channels
#define NBLK_A 144                 // 3 attns * 48 batches
#define TPB_A 512

// scratch (allocation-free rule: __device__ globals)
__device__ float g_att[NROWS * 9];       // (B,S,9) attention outputs
__device__ float g_part[NBLK_A * 6];     // per-block partial sums/sumsq (3 ch each)

// ---------------------------------------------------------------------------
// Kernel A: fused per-band projection + cross attention + BN partial stats
// block = (attn_idx, batch). K,V tiles live in smem; each thread owns 2 rows.
// ---------------------------------------------------------------------------
__global__ __launch_bounds__(TPB_A) void attn_kernel(
    const float* __restrict__ x,
    const float* __restrict__ WQ, const float* __restrict__ bQ,
    const float* __restrict__ WK, const float* __restrict__ bK,
    const float* __restrict__ WV, const float* __restrict__ bV)
{
    __shared__ float4 Ks[SEQ];
    __shared__ float4 Vs[SEQ];
    __shared__ float  sred[16 * 6];

    const int blk  = blockIdx.x;
    const int attn = blk / NB;          // 0..2
    const int b    = blk - attn * NB;   // 0..47

    // a1 = attn(Q[2],K[0],V[1]); a2 = attn(Q[0],K[1],V[2]); a3 = attn(Q[1],K[2],V[0])
    const int qmap[3] = {2, 0, 1};
    const int kmap[3] = {0, 1, 2};
    const int vmap[3] = {1, 2, 0};
    const int qb = qmap[attn], kb = kmap[attn], vb = vmap[attn];

    const int tid = threadIdx.x;

    // ---- phase 1: build K,V tiles in smem (3x3 proj on the fly) ----
    {
        const float* wk = WK + kb * 9;  const float* bk = bK + kb * 3;
        const float* wv = WV + vb * 9;  const float* bv = bV + vb * 3;
        #pragma unroll
        for (int it = 0; it < SEQ / TPB_A; ++it) {
            int t = tid + it * TPB_A;
            const float* xk = x + ((size_t)(kb * NB + b) * SEQ + t) * 3;
            float x0 = xk[0], x1 = xk[1], x2 = xk[2];
            float k0 = fmaf(wk[0], x0, fmaf(wk[1], x1, fmaf(wk[2], x2, bk[0])));
            float k1 = fmaf(wk[3], x0, fmaf(wk[4], x1, fmaf(wk[5], x2, bk[1])));
            float k2 = fmaf(wk[6], x0, fmaf(wk[7], x1, fmaf(wk[8], x2, bk[2])));
            Ks[t] = make_float4(k0, k1, k2, 0.0f);

            const float* xv = x + ((size_t)(vb * NB + b) * SEQ + t) * 3;
            float y0 = xv[0], y1 = xv[1], y2 = xv[2];
            float v0 = fmaf(wv[0], y0, fmaf(wv[1], y1, fmaf(wv[2], y2, bv[0])));
            float v1 = fmaf(wv[3], y0, fmaf(wv[4], y1, fmaf(wv[5], y2, bv[1])));
            float v2 = fmaf(wv[6], y0, fmaf(wv[7], y1, fmaf(wv[8], y2, bv[2])));
            Vs[t] = make_float4(v0, v1, v2, 0.0f);
        }
    }
    __syncthreads();

    // ---- phase 2: each thread handles rows s0 = tid and s1 = tid+512 ----
    // fold 1/sqrt(3) (softmax scale) and log2(e) (for ex2) into q
    const float qscale = 1.4426950408889634f / 1.7320508075688772f;

    float q00, q01, q02, q10, q11, q12;
    {
        const float* wq = WQ + qb * 9;  const float* bq = bQ + qb * 3;
        const int s0 = tid, s1 = tid + TPB_A;
        const float* xq = x + ((size_t)(qb * NB + b) * SEQ + s0) * 3;
        float x0 = xq[0], x1 = xq[1], x2 = xq[2];
        q00 = fmaf(wq[0], x0, fmaf(wq[1], x1, fmaf(wq[2], x2, bq[0]))) * qscale;
        q01 = fmaf(wq[3], x0, fmaf(wq[4], x1, fmaf(wq[5], x2, bq[1]))) * qscale;
        q02 = fmaf(wq[6], x0, fmaf(wq[7], x1, fmaf(wq[8], x2, bq[2]))) * qscale;
        xq = x + ((size_t)(qb * NB + b) * SEQ + s1) * 3;
        x0 = xq[0]; x1 = xq[1]; x2 = xq[2];
        q10 = fmaf(wq[0], x0, fmaf(wq[1], x1, fmaf(wq[2], x2, bq[0]))) * qscale;
        q11 = fmaf(wq[3], x0, fmaf(wq[4], x1, fmaf(wq[5], x2, bq[1]))) * qscale;
        q12 = fmaf(wq[6], x0, fmaf(wq[7], x1, fmaf(wq[8], x2, bq[2]))) * qscale;
    }

    float4 a0 = make_float4(0.f, 0.f, 0.f, 0.f);
    float4 a1 = make_float4(0.f, 0.f, 0.f, 0.f);

    #pragma unroll 8
    for (int t = 0; t < SEQ; ++t) {
        float4 k = Ks[t];
        float4 v = Vs[t];
        float d0 = fmaf(q00, k.x, fmaf(q01, k.y, q02 * k.z));
        float d1 = fmaf(q10, k.x, fmaf(q11, k.y, q12 * k.z));
        float e0, e1;
        asm("ex2.approx.f32 %0, %1;" : "=f"(e0) : "f"(d0));
        asm("ex2.approx.f32 %0, %1;" : "=f"(e1) : "f"(d1));
        a0.x = fmaf(e0, v.x, a0.x);
        a0.y = fmaf(e0, v.y, a0.y);
        a0.z = fmaf(e0, v.z, a0.z);
        a0.w += e0;
        a1.x = fmaf(e1, v.x, a1.x);
        a1.y = fmaf(e1, v.y, a1.y);
        a1.z = fmaf(e1, v.z, a1.z);
        a1.w += e1;
    }

    const float inv0 = 1.0f / a0.w;
    const float inv1 = 1.0f / a1.w;
    const float o00 = a0.x * inv0, o01 = a0.y * inv0, o02 = a0.z * inv0;
    const float o10 = a1.x * inv1, o11 = a1.y * inv1, o12 = a1.z * inv1;

    {
        float* dst = g_att + ((size_t)b * SEQ + tid) * 9 + attn * 3;
        dst[0] = o00; dst[1] = o01; dst[2] = o02;
        dst = g_att + ((size_t)b * SEQ + (tid + TPB_A)) * 9 + attn * 3;
        dst[0] = o10; dst[1] = o11; dst[2] = o12;
    }

    // ---- BN partial stats (deterministic block reduction) ----
    float sm[3], sq[3];
    sm[0] = o00 + o10; sm[1] = o01 + o11; sm[2] = o02 + o12;
    sq[0] = o00 * o00 + o10 * o10;
    sq[1] = o01 * o01 + o11 * o11;
    sq[2] = o02 * o02 + o12 * o12;

    #pragma unroll
    for (int off = 16; off > 0; off >>= 1) {
        #pragma unroll
        for (int i = 0; i < 3; ++i) {
            sm[i] += __shfl_down_sync(0xFFFFFFFFu, sm[i], off);
            sq[i] += __shfl_down_sync(0xFFFFFFFFu, sq[i], off);
        }
    }
    const int warp = tid >> 5, lane = tid & 31;
    if (lane == 0) {
        #pragma unroll
        for (int i = 0; i < 3; ++i) {
            sred[warp * 6 + i]     = sm[i];
            sred[warp * 6 + 3 + i] = sq[i];
        }
    }
    __syncthreads();
    if (tid == 0) {
        float acc[6] = {0.f, 0.f, 0.f, 0.f, 0.f, 0.f};
        #pragma unroll
        for (int w = 0; w < 16; ++w)
            #pragma unroll
            for (int i = 0; i < 6; ++i)
                acc[i] += sred[w * 6 + i];
        #pragma unroll
        for (int i = 0; i < 6; ++i)
            g_part[blk * 6 + i] = acc[i];
    }
}

// ---------------------------------------------------------------------------
// Kernel B: finalize BN stats (redundantly per block, deterministic) + BN + FC
// ---------------------------------------------------------------------------
__global__ __launch_bounds__(256) void bnfc_kernel(
    const float* __restrict__ gamma, const float* __restrict__ beta,
    const float* __restrict__ fcw, const float* __restrict__ fcb,
    float* __restrict__ out)
{
    __shared__ float sscale[9], sshift[9];
    const int tid = threadIdx.x;
    if (tid < 9) {
        const int at = tid / 3, d = tid - at * 3;
        float sm = 0.f, sq = 0.f;
        for (int i = 0; i < NB; ++i) {
            const float* p = g_part + (size_t)(at * NB + i) * 6;
            sm += p[d];
            sq += p[3 + d];
        }
        const float mean = sm * (1.0f / NROWS);
        const float var  = sq * (1.0f / NROWS) - mean * mean;
        const float inv  = 1.0f / sqrtf(var + 1e-5f);
        const float sc   = gamma[tid] * inv;
        sscale[tid] = sc;
        sshift[tid] = beta[tid] - mean * sc;
    }
    __syncthreads();

    const int row = blockIdx.x * 256 + tid;
    if (row < NROWS) {
        const float* a = g_att + (size_t)row * 9;
        float n[9];
        #pragma unroll
        for (int c = 0; c < 9; ++c)
            n[c] = fmaf(a[c], sscale[c], sshift[c]);
        #pragma unroll
        for (int j = 0; j < 3; ++j) {
            float y = fcb[j];
            #pragma unroll
            for (int c = 0; c < 9; ++c)
                y = fmaf(n[c], fcw[j * 9 + c], y);
            out[row * 3 + j] = y;
        }
    }
}

// ---------------------------------------------------------------------------
extern "C" void kernel_launch(void* const* d_in, const int* in_sizes, int n_in,
                              void* d_out, int out_size)
{
    const float* x     = (const float*)d_in[0];
    const float* WQ    = (const float*)d_in[1];
    const float* bQ    = (const float*)d_in[2];
    const float* WK    = (const float*)d_in[3];
    const float* bK    = (const float*)d_in[4];
    const float* WV    = (const float*)d_in[5];
    const float* bV    = (const float*)d_in[6];
    const float* gamma = (const float*)d_in[7];
    const float* beta  = (const float*)d_in[8];
    const float* fcw   = (const float*)d_in[9];
    const float* fcb   = (const float*)d_in[10];

    attn_kernel<<<NBLK_A, TPB_A>>>(x, WQ, bQ, WK, bK, WV, bV);
    bnfc_kernel<<<(NROWS + 255) / 256, 256>>>(gamma, beta, fcw, fcb, (float*)d_out);
}